// round 14
// baseline (speedup 1.0000x reference)
#include <cuda_runtime.h>
#include <cuda_bf16.h>
#include <cstdint>

#define N_NODES   50000
#define N_EDGES   600000
#define EMBED     128
#define HIDDEN    128
#define NUM_TYPES 16

// Scratch (device globals: allocation-free rule)
__device__ float g_x[N_NODES * EMBED];       // x (layer-1 input)
__device__ float g_agg[N_NODES * EMBED];     // neighbor MEAN (layer 1)
__device__ float g_h1[N_NODES * EMBED];      // layer-1 output
__device__ int   g_deg[N_NODES];
__device__ float g_z[N_NODES * NUM_TYPES];   // h1 @ Wlc
__device__ float g_r[N_NODES * NUM_TYPES];   // h1 @ Wrc + bf
__device__ float g_Wlc[HIDDEN * NUM_TYPES];  // W2_l @ Wc
__device__ float g_Wrc[HIDDEN * NUM_TYPES];  // W2_r @ Wc
__device__ float g_bf[NUM_TYPES];            // b2 @ Wc + bc
// bf16 hi/lo packed layer-1 weights, [n][kpair] (virtual K=256: Wl | Wr)
__device__ uint32_t g_Wh[HIDDEN * 128];
__device__ uint32_t g_Wlo[HIDDEN * 128];
// CSR (edges grouped by dst)
__device__ int g_rowptr[N_NODES + 1];
__device__ int g_cursor[N_NODES];
__device__ int g_csrc[N_EDGES];
__device__ int g_bsum[256];

// ---------------------------------------------------------------------------
// helpers
// ---------------------------------------------------------------------------
__device__ __forceinline__ void split2(float x, float y, uint32_t& hi, uint32_t& lo) {
    __nv_bfloat16 hx = __float2bfloat16(x), hy = __float2bfloat16(y);
    float rx = x - __bfloat162float(hx);
    float ry = y - __bfloat162float(hy);
    __nv_bfloat162 H; H.x = hx; H.y = hy;
    __nv_bfloat162 L; L.x = __float2bfloat16(rx); L.y = __float2bfloat16(ry);
    hi = *reinterpret_cast<uint32_t*>(&H);
    lo = *reinterpret_cast<uint32_t*>(&L);
}
__device__ __forceinline__ void mma16(float* d, const uint32_t* a, const uint32_t* b) {
    asm volatile(
        "mma.sync.aligned.m16n8k16.row.col.f32.bf16.bf16.f32 "
        "{%0,%1,%2,%3}, {%4,%5,%6,%7}, {%8,%9}, {%0,%1,%2,%3};"
        : "+f"(d[0]), "+f"(d[1]), "+f"(d[2]), "+f"(d[3])
        : "r"(a[0]), "r"(a[1]), "r"(a[2]), "r"(a[3]), "r"(b[0]), "r"(b[1]));
}

// ---------------------------------------------------------------------------
// Kernel: merged init.
//   blocks [0,64): pack W1_l|W1_r -> bf16 hi/lo [n][kpair]
//   blocks [64,66): fold classifier into layer-2 weights (Wlc/Wrc/bf)
//   blocks [66,..): zero g_deg
// ---------------------------------------------------------------------------
__global__ void __launch_bounds__(256) k_init(
        const float* __restrict__ W1_l, const float* __restrict__ W1_r,
        const float* __restrict__ W2_l, const float* __restrict__ W2_r,
        const float* __restrict__ Wc,   const float* __restrict__ b2,
        const float* __restrict__ bc) {
    __shared__ float wcs[HIDDEN * NUM_TYPES];
    const int b   = blockIdx.x;
    const int tid = threadIdx.x;

    if (b < 64) {
        int idx = b * 256 + tid;              // 0..16383
        int n  = idx >> 7;
        int kp = idx & 127;
        int k  = kp * 2;
        const float* Wsrc = (k < 128) ? W1_l : W1_r;
        int kk = k & 127;
        float v0 = Wsrc[kk * 128 + n];
        float v1 = Wsrc[(kk + 1) * 128 + n];
        uint32_t hi, lo;
        split2(v0, v1, hi, lo);
        g_Wh[n * 128 + kp]  = hi;
        g_Wlo[n * 128 + kp] = lo;
        return;
    }
    if (b < 66) {
#pragma unroll
        for (int i = 0; i < 8; ++i) wcs[tid + i * 256] = Wc[tid + i * 256];
        __syncthreads();
        if (tid < 128) {
            const float* Win = (b == 64) ? W2_l : W2_r;
            float* Wout      = (b == 64) ? g_Wlc : g_Wrc;
            float4 a0 = make_float4(0,0,0,0), a1 = a0, a2 = a0, a3 = a0;
            const float* row = Win + tid * HIDDEN;
#pragma unroll 4
            for (int t = 0; t < HIDDEN; ++t) {
                float w = row[t];
                float4 c0 = *(const float4*)&wcs[t * 16 + 0];
                float4 c1 = *(const float4*)&wcs[t * 16 + 4];
                float4 c2 = *(const float4*)&wcs[t * 16 + 8];
                float4 c3 = *(const float4*)&wcs[t * 16 + 12];
                a0.x = fmaf(w, c0.x, a0.x); a0.y = fmaf(w, c0.y, a0.y);
                a0.z = fmaf(w, c0.z, a0.z); a0.w = fmaf(w, c0.w, a0.w);
                a1.x = fmaf(w, c1.x, a1.x); a1.y = fmaf(w, c1.y, a1.y);
                a1.z = fmaf(w, c1.z, a1.z); a1.w = fmaf(w, c1.w, a1.w);
                a2.x = fmaf(w, c2.x, a2.x); a2.y = fmaf(w, c2.y, a2.y);
                a2.z = fmaf(w, c2.z, a2.z); a2.w = fmaf(w, c2.w, a2.w);
                a3.x = fmaf(w, c3.x, a3.x); a3.y = fmaf(w, c3.y, a3.y);
                a3.z = fmaf(w, c3.z, a3.z); a3.w = fmaf(w, c3.w, a3.w);
            }
            *(float4*)&Wout[tid * 16 + 0]  = a0;
            *(float4*)&Wout[tid * 16 + 4]  = a1;
            *(float4*)&Wout[tid * 16 + 8]  = a2;
            *(float4*)&Wout[tid * 16 + 12] = a3;

            if (b == 65 && tid < NUM_TYPES) {
                float s = bc[tid];
                for (int t = 0; t < HIDDEN; ++t) s = fmaf(b2[t], wcs[t * 16 + tid], s);
                g_bf[tid] = s;
            }
        }
        return;
    }
    int idx = (b - 66) * 256 + tid;
    if (idx < N_NODES) g_deg[idx] = 0;
}

// ---------------------------------------------------------------------------
// Kernel 1: gather x = emb[entity]
// ---------------------------------------------------------------------------
__global__ void k_prep(const int* __restrict__ entity, const float* __restrict__ emb) {
    int node = blockIdx.x * 8 + (threadIdx.x >> 5);
    int lane = threadIdx.x & 31;
    if (node >= N_NODES) return;
    int e = entity[node];
    float4 v = ((const float4*)emb)[e * 32 + lane];
    ((float4*)g_x)[node * 32 + lane] = v;
}

__global__ void k_deg(const int* __restrict__ dst) {
    int e = blockIdx.x * blockDim.x + threadIdx.x;
    if (e < N_EDGES) atomicAdd(&g_deg[dst[e]], 1);
}

// ---------------------------------------------------------------------------
// CSR build: block sums -> scan of sums -> per-block exclusive scan + fill.
// ---------------------------------------------------------------------------
__global__ void __launch_bounds__(256) k_scan1() {
    __shared__ int s[256];
    int idx = blockIdx.x * 256 + threadIdx.x;
    int v = (idx < N_NODES) ? g_deg[idx] : 0;
    s[threadIdx.x] = v;
    __syncthreads();
#pragma unroll
    for (int off = 128; off > 0; off >>= 1) {
        if (threadIdx.x < off) s[threadIdx.x] += s[threadIdx.x + off];
        __syncthreads();
    }
    if (threadIdx.x == 0) g_bsum[blockIdx.x] = s[0];
}

__global__ void __launch_bounds__(256) k_scan2(int nblocks) {
    __shared__ int s[256];
    int t = threadIdx.x;
    int v = (t < nblocks) ? g_bsum[t] : 0;
    s[t] = v;
    __syncthreads();
#pragma unroll
    for (int off = 1; off < 256; off <<= 1) {
        int x = (t >= off) ? s[t - off] : 0;
        __syncthreads();
        s[t] += x;
        __syncthreads();
    }
    if (t < nblocks) g_bsum[t] = s[t] - v;   // exclusive
}

__global__ void __launch_bounds__(256) k_scan3() {
    __shared__ int s[256];
    int idx = blockIdx.x * 256 + threadIdx.x;
    int t = threadIdx.x;
    int v = (idx < N_NODES) ? g_deg[idx] : 0;
    s[t] = v;
    __syncthreads();
#pragma unroll
    for (int off = 1; off < 256; off <<= 1) {
        int x = (t >= off) ? s[t - off] : 0;
        __syncthreads();
        s[t] += x;
        __syncthreads();
    }
    if (idx < N_NODES) {
        int excl = g_bsum[blockIdx.x] + s[t] - v;
        g_rowptr[idx] = excl;
        g_cursor[idx] = excl;
        if (idx == N_NODES - 1) g_rowptr[N_NODES] = excl + v;
    }
}

__global__ void k_fill(const int* __restrict__ src, const int* __restrict__ dst) {
    int e = blockIdx.x * blockDim.x + threadIdx.x;
    if (e >= N_EDGES) return;
    int d = dst[e];
    int pos = atomicAdd(&g_cursor[d], 1);
    g_csrc[pos] = src[e];
}

// ---------------------------------------------------------------------------
// Kernel: gather-aggregate 128-wide. One warp per node; writes the MEAN.
// ---------------------------------------------------------------------------
__global__ void __launch_bounds__(256) k_gather(void) {
    int node = blockIdx.x * 8 + (threadIdx.x >> 5);
    int lane = threadIdx.x & 31;
    if (node >= N_NODES) return;
    int start = g_rowptr[node];
    int end   = g_rowptr[node + 1];

    float4 a0 = make_float4(0.f, 0.f, 0.f, 0.f);
    float4 a1 = a0, a2 = a0, a3 = a0;
    int j = start;
    for (; j + 3 < end; j += 4) {
        int s0 = g_csrc[j];
        int s1 = g_csrc[j + 1];
        int s2 = g_csrc[j + 2];
        int s3 = g_csrc[j + 3];
        float4 v0 = ((const float4*)g_x)[s0 * 32 + lane];
        float4 v1 = ((const float4*)g_x)[s1 * 32 + lane];
        float4 v2 = ((const float4*)g_x)[s2 * 32 + lane];
        float4 v3 = ((const float4*)g_x)[s3 * 32 + lane];
        a0.x += v0.x; a0.y += v0.y; a0.z += v0.z; a0.w += v0.w;
        a1.x += v1.x; a1.y += v1.y; a1.z += v1.z; a1.w += v1.w;
        a2.x += v2.x; a2.y += v2.y; a2.z += v2.z; a2.w += v2.w;
        a3.x += v3.x; a3.y += v3.y; a3.z += v3.z; a3.w += v3.w;
    }
    for (; j < end; ++j) {
        int s0 = g_csrc[j];
        float4 v0 = ((const float4*)g_x)[s0 * 32 + lane];
        a0.x += v0.x; a0.y += v0.y; a0.z += v0.z; a0.w += v0.w;
    }
    int dg = end - start;
    float inv = 1.0f / (float)(dg > 1 ? dg : 1);
    float4 r = make_float4((a0.x + a1.x + a2.x + a3.x) * inv,
                           (a0.y + a1.y + a2.y + a3.y) * inv,
                           (a0.z + a1.z + a2.z + a3.z) * inv,
                           (a0.w + a1.w + a2.w + a3.w) * inv);
    ((float4*)g_agg)[node * 32 + lane] = r;
}

// ---------------------------------------------------------------------------
// Kernel 4: SAGE layer-1 via mma.sync bf16 m16n8k16 (3-way split), relu.
// BM=64, BN=128, 8 warps (2m x 4n), warp tile 32x32, virtual K=256 (agg|x).
// Double-buffered smem (36KB), 782 blocks -> better wave balance, 3 CTAs/SM.
// smem (u32): sAh[2],sAl[2]: 768 each; sBh[2],sBl[2]: 1536 each.
// ---------------------------------------------------------------------------
__global__ void __launch_bounds__(256, 3) k_layer_bf16(
        const float* __restrict__ bias, const float* __restrict__ xin,
        float* __restrict__ outp) {
    extern __shared__ uint32_t dsm[];

    const int tid = threadIdx.x;
    const int m0  = blockIdx.x * 64;

    uint32_t* sAh[2] = { dsm + 0 * 768, dsm + 2 * 768 };
    uint32_t* sAl[2] = { dsm + 1 * 768, dsm + 3 * 768 };
    uint32_t* sBh[2] = { dsm + 3072 + 0 * 1536, dsm + 3072 + 2 * 1536 };
    uint32_t* sBl[2] = { dsm + 3072 + 1 * 1536, dsm + 3072 + 3 * 1536 };

    const int w    = tid >> 5;
    const int lane = tid & 31;
    const int g    = lane >> 2;
    const int tg   = lane & 3;
    const int wm   = (w >> 2) << 5;     // 0,32
    const int wn   = (w & 3) << 5;      // 0,32,64,96

    // A loader: 256 threads cover 64 rows x 4 k-quads (one float4 each)
    const int a_m  = tid >> 2;          // 0..63
    const int a_kq = (tid & 3) << 2;    // 0,4,8,12
    // B loader: 128 n x 2 halves
    const int b_n    = tid >> 1;
    const int b_half = (tid & 1) << 2;

    float acc[2][4][4];
#pragma unroll
    for (int mt = 0; mt < 2; ++mt)
#pragma unroll
        for (int nt = 0; nt < 4; ++nt)
#pragma unroll
            for (int q = 0; q < 4; ++q) acc[mt][nt][q] = 0.f;

    float4 aIn;
    uint4  bInH, bInL;

#define LOAD_AB(c) do {                                                        \
        const int kb = (c) * 16;                                               \
        {                                                                      \
            const int gm = m0 + a_m;                                           \
            float4 v = make_float4(0.f, 0.f, 0.f, 0.f);                        \
            if (gm < N_NODES) {                                                \
                if (kb < 128)                                                  \
                    v = *(const float4*)(g_agg + (size_t)gm * 128 + kb + a_kq);\
                else                                                           \
                    v = *(const float4*)(xin + (size_t)gm * 128 + (kb - 128) + a_kq); \
            }                                                                  \
            aIn = v;                                                           \
        }                                                                      \
        {                                                                      \
            const int goff = b_n * 128 + (c) * 8 + b_half;                     \
            bInH = *(const uint4*)&g_Wh[goff];                                 \
            bInL = *(const uint4*)&g_Wlo[goff];                                \
        }                                                                      \
    } while (0)

#define STORE_AB(buf) do {                                                     \
        {                                                                      \
            uint32_t h0, l0, h1, l1;                                           \
            split2(aIn.x, aIn.y, h0, l0);                                      \
            split2(aIn.z, aIn.w, h1, l1);                                      \
            const int base = a_m * 12 + (a_kq >> 1);                           \
            sAh[buf][base]     = h0;                                           \
            sAh[buf][base + 1] = h1;                                           \
            sAl[buf][base]     = l0;                                           \
            sAl[buf][base + 1] = l1;                                           \
        }                                                                      \
        {                                                                      \
            const int base = b_n * 12 + b_half;                                \
            *(uint4*)&sBh[buf][base] = bInH;                                   \
            *(uint4*)&sBl[buf][base] = bInL;                                   \
        }                                                                      \
    } while (0)

    LOAD_AB(0);
    STORE_AB(0);
    __syncthreads();

    for (int c = 0; c < 16; ++c) {
        const int cur = c & 1;
        if (c < 15) LOAD_AB(c + 1);

        const uint32_t* Ah = sAh[cur];
        const uint32_t* Al = sAl[cur];
        const uint32_t* Bh = sBh[cur];
        const uint32_t* Bl = sBl[cur];

        uint32_t ah[2][4], al[2][4];
#pragma unroll
        for (int mt = 0; mt < 2; ++mt) {
            const int mb = wm + mt * 16;
            const int r0 = (mb + g) * 12;
            const int r1 = (mb + g + 8) * 12;
            ah[mt][0] = Ah[r0 + tg];
            ah[mt][1] = Ah[r1 + tg];
            ah[mt][2] = Ah[r0 + tg + 4];
            ah[mt][3] = Ah[r1 + tg + 4];
            al[mt][0] = Al[r0 + tg];
            al[mt][1] = Al[r1 + tg];
            al[mt][2] = Al[r0 + tg + 4];
            al[mt][3] = Al[r1 + tg + 4];
        }
#pragma unroll
        for (int nt = 0; nt < 4; ++nt) {
            const int nb = (wn + nt * 8 + g) * 12;
            uint32_t bh[2] = { Bh[nb + tg], Bh[nb + tg + 4] };
            uint32_t bl[2] = { Bl[nb + tg], Bl[nb + tg + 4] };
#pragma unroll
            for (int mt = 0; mt < 2; ++mt) {
                mma16(acc[mt][nt], ah[mt], bh);
                mma16(acc[mt][nt], al[mt], bh);
                mma16(acc[mt][nt], ah[mt], bl);
            }
        }

        if (c < 15) STORE_AB(cur ^ 1);
        __syncthreads();
    }
#undef LOAD_AB
#undef STORE_AB

    // epilogue: bias + relu + float2 stores
#pragma unroll
    for (int nt = 0; nt < 4; ++nt) {
        const int col = wn + nt * 8 + 2 * tg;
        const float2 bv = *(const float2*)(bias + col);
#pragma unroll
        for (int mt = 0; mt < 2; ++mt) {
            const int r0 = m0 + wm + mt * 16 + g;
            const int r1 = r0 + 8;
            float v0 = acc[mt][nt][0] + bv.x;
            float v1 = acc[mt][nt][1] + bv.y;
            float v2 = acc[mt][nt][2] + bv.x;
            float v3 = acc[mt][nt][3] + bv.y;
            v0 = v0 > 0.f ? v0 : 0.f;
            v1 = v1 > 0.f ? v1 : 0.f;
            v2 = v2 > 0.f ? v2 : 0.f;
            v3 = v3 > 0.f ? v3 : 0.f;
            if (r0 < N_NODES)
                *(float2*)(outp + (size_t)r0 * 128 + col) = make_float2(v0, v1);
            if (r1 < N_NODES)
                *(float2*)(outp + (size_t)r1 * 128 + col) = make_float2(v2, v3);
        }
    }
}

// ---------------------------------------------------------------------------
// Kernel: z = h1 @ Wlc ; r = h1 @ Wrc + bf.
// ---------------------------------------------------------------------------
__global__ void __launch_bounds__(256) k_zr(const float* __restrict__ h1) {
    __shared__ float hs[16][128];
    __shared__ float wl[16][132];
    __shared__ float wr[16][132];
    __shared__ float bfs[16];
    const int tid = threadIdx.x;

#pragma unroll
    for (int i = 0; i < 8; ++i) {
        int idx = tid + i * 256;
        int k = idx >> 4, c = idx & 15;
        wl[c][k] = g_Wlc[idx];
        wr[c][k] = g_Wrc[idx];
    }
    if (tid < 16) bfs[tid] = g_bf[tid];

    const int n0 = blockIdx.x * 16;
#pragma unroll
    for (int i = 0; i < 2; ++i) {
        int idx = tid + i * 256;
        int rr = n0 + (idx >> 5);
        float4 v = (rr < N_NODES) ? ((const float4*)h1)[rr * 32 + (idx & 31)]
                                  : make_float4(0.f, 0.f, 0.f, 0.f);
        ((float4*)&hs[0][0])[idx] = v;
    }
    __syncthreads();

    const int node = tid >> 4;
    const int col  = tid & 15;
    float zs = 0.f, rs = bfs[col];
#pragma unroll
    for (int k4 = 0; k4 < 32; ++k4) {
        float4 h = *(const float4*)&hs[node][k4 * 4];
        float4 a = *(const float4*)&wl[col][k4 * 4];
        float4 b = *(const float4*)&wr[col][k4 * 4];
        zs = fmaf(h.x, a.x, zs); zs = fmaf(h.y, a.y, zs);
        zs = fmaf(h.z, a.z, zs); zs = fmaf(h.w, a.w, zs);
        rs = fmaf(h.x, b.x, rs); rs = fmaf(h.y, b.y, rs);
        rs = fmaf(h.z, b.z, rs); rs = fmaf(h.w, b.w, rs);
    }
    int gn = n0 + node;
    if (gn < N_NODES) {
        g_z[gn * 16 + col] = zs;
        g_r[gn * 16 + col] = rs;
    }
}

// ---------------------------------------------------------------------------
// Kernel: out[n,c] = mean_{j->n}(z[j,c]) + r[n,c]   (gather, fused comb)
// ---------------------------------------------------------------------------
__global__ void __launch_bounds__(256) k_comb2(float* __restrict__ out) {
    int idx = blockIdx.x * 256 + threadIdx.x;
    int n = idx >> 4;
    if (n >= N_NODES) return;
    int c = idx & 15;
    int start = g_rowptr[n];
    int end   = g_rowptr[n + 1];
    float a0 = 0.f, a1 = 0.f, a2 = 0.f, a3 = 0.f;
    int j = start;
    for (; j + 3 < end; j += 4) {
        int s0 = g_csrc[j];
        int s1 = g_csrc[j + 1];
        int s2 = g_csrc[j + 2];
        int s3 = g_csrc[j + 3];
        a0 += g_z[s0 * 16 + c];
        a1 += g_z[s1 * 16 + c];
        a2 += g_z[s2 * 16 + c];
        a3 += g_z[s3 * 16 + c];
    }
    for (; j < end; ++j) a0 += g_z[g_csrc[j] * 16 + c];
    int dg = end - start;
    float inv = 1.0f / (float)(dg > 1 ? dg : 1);
    out[idx] = fmaf((a0 + a1) + (a2 + a3), inv, g_r[idx]);
}

// ---------------------------------------------------------------------------
extern "C" void kernel_launch(void* const* d_in, const int* in_sizes, int n_in,
                              void* d_out, int out_size) {
    const int*   entity = (const int*)d_in[0];
    const int*   eidx   = (const int*)d_in[1];
    const float* emb    = (const float*)d_in[2];
    const float* W1_l   = (const float*)d_in[3];
    const float* b1     = (const float*)d_in[4];
    const float* W1_r   = (const float*)d_in[5];
    const float* W2_l   = (const float*)d_in[6];
    const float* b2     = (const float*)d_in[7];
    const float* W2_r   = (const float*)d_in[8];
    const float* Wc     = (const float*)d_in[9];
    const float* bc     = (const float*)d_in[10];
    float* out = (float*)d_out;

    const int* src = eidx;            // edge_index[0]
    const int* dst = eidx + N_EDGES;  // edge_index[1]

    float* d_x  = nullptr; cudaGetSymbolAddress((void**)&d_x,  g_x);
    float* d_h1 = nullptr; cudaGetSymbolAddress((void**)&d_h1, g_h1);

    const int GEMM_BLOCKS = (N_NODES + 63) / 64;       // 782
    const int SCAN_BLOCKS = (N_NODES + 255) / 256;     // 196
    const int INIT_BLOCKS = 66 + SCAN_BLOCKS;          // wprep + wfuse + degzero
    const int SMEM_LAYER  = 9216 * 4;                  // 36 KB dynamic

    cudaFuncSetAttribute(k_layer_bf16, cudaFuncAttributeMaxDynamicSharedMemorySize,
                         SMEM_LAYER);

    // merged weight precompute + deg zero
    k_init<<<INIT_BLOCKS, 256>>>(W1_l, W1_r, W2_l, W2_r, Wc, b2, bc);
    // gather x
    k_prep<<<(N_NODES + 7) / 8, 256>>>(entity, emb);
    // CSR build
    k_deg<<<(N_EDGES + 255) / 256, 256>>>(dst);
    k_scan1<<<SCAN_BLOCKS, 256>>>();
    k_scan2<<<1, 256>>>(SCAN_BLOCKS);
    k_scan3<<<SCAN_BLOCKS, 256>>>();
    k_fill<<<(N_EDGES + 255) / 256, 256>>>(src, dst);
    // gather-aggregate mean of x
    k_gather<<<(N_NODES + 7) / 8, 256>>>();
    // layer 1 (relu) -> h1
    k_layer_bf16<<<GEMM_BLOCKS, 256, SMEM_LAYER>>>(b1, d_x, d_h1);
    // z = h1@Wlc, r = h1@Wrc + bf
    k_zr<<<(N_NODES + 15) / 16, 256>>>(d_h1);
    // fused gather mean of z + combine
    k_comb2<<<(N_NODES * 16 + 255) / 256, 256>>>(out);
}

// round 17
// speedup vs baseline: 1.0780x; 1.0780x over previous
#include <cuda_runtime.h>
#include <cuda_bf16.h>
#include <cstdint>

#define N_NODES   50000
#define N_EDGES   600000
#define EMBED     128
#define HIDDEN    128
#define NUM_TYPES 16

// Scratch (device globals: allocation-free rule)
__device__ float g_x[N_NODES * EMBED];       // x (layer-1 input)
__device__ float g_agg[N_NODES * EMBED];     // neighbor MEAN (layer 1)
__device__ float g_h1[N_NODES * EMBED];      // layer-1 output
__device__ int   g_deg[N_NODES];
__device__ float g_z[N_NODES * NUM_TYPES];   // h1 @ Wlc
__device__ float g_r[N_NODES * NUM_TYPES];   // h1 @ Wrc + bf
__device__ float g_Wlc[HIDDEN * NUM_TYPES];  // W2_l @ Wc
__device__ float g_Wrc[HIDDEN * NUM_TYPES];  // W2_r @ Wc
__device__ float g_bf[NUM_TYPES];            // b2 @ Wc + bc
// bf16 hi/lo packed layer-1 weights, [n][kpair] (virtual K=256: Wl | Wr)
__device__ uint32_t g_Wh[HIDDEN * 128];
__device__ uint32_t g_Wlo[HIDDEN * 128];
// CSR (edges grouped by dst)
__device__ int g_rowptr[N_NODES + 1];
__device__ int g_cursor[N_NODES];
__device__ int g_csrc[N_EDGES];
__device__ int g_bsum[256];
__device__ int g_scancnt;    // zero-initialized; last block resets to 0 each run

// ---------------------------------------------------------------------------
// helpers
// ---------------------------------------------------------------------------
__device__ __forceinline__ void split2(float x, float y, uint32_t& hi, uint32_t& lo) {
    __nv_bfloat16 hx = __float2bfloat16(x), hy = __float2bfloat16(y);
    float rx = x - __bfloat162float(hx);
    float ry = y - __bfloat162float(hy);
    __nv_bfloat162 H; H.x = hx; H.y = hy;
    __nv_bfloat162 L; L.x = __float2bfloat16(rx); L.y = __float2bfloat16(ry);
    hi = *reinterpret_cast<uint32_t*>(&H);
    lo = *reinterpret_cast<uint32_t*>(&L);
}
__device__ __forceinline__ void mma16(float* d, const uint32_t* a, const uint32_t* b) {
    asm volatile(
        "mma.sync.aligned.m16n8k16.row.col.f32.bf16.bf16.f32 "
        "{%0,%1,%2,%3}, {%4,%5,%6,%7}, {%8,%9}, {%0,%1,%2,%3};"
        : "+f"(d[0]), "+f"(d[1]), "+f"(d[2]), "+f"(d[3])
        : "r"(a[0]), "r"(a[1]), "r"(a[2]), "r"(a[3]), "r"(b[0]), "r"(b[1]));
}

// ---------------------------------------------------------------------------
// Kernel: merged init.
//   blocks [0,64): pack W1_l|W1_r -> bf16 hi/lo [n][kpair]
//   blocks [64,66): fold classifier into layer-2 weights (Wlc/Wrc/bf)
//   blocks [66,..): zero g_deg
// ---------------------------------------------------------------------------
__global__ void __launch_bounds__(256) k_init(
        const float* __restrict__ W1_l, const float* __restrict__ W1_r,
        const float* __restrict__ W2_l, const float* __restrict__ W2_r,
        const float* __restrict__ Wc,   const float* __restrict__ b2,
        const float* __restrict__ bc) {
    __shared__ float wcs[HIDDEN * NUM_TYPES];
    const int b   = blockIdx.x;
    const int tid = threadIdx.x;

    if (b < 64) {
        int idx = b * 256 + tid;              // 0..16383
        int n  = idx >> 7;
        int kp = idx & 127;
        int k  = kp * 2;
        const float* Wsrc = (k < 128) ? W1_l : W1_r;
        int kk = k & 127;
        float v0 = Wsrc[kk * 128 + n];
        float v1 = Wsrc[(kk + 1) * 128 + n];
        uint32_t hi, lo;
        split2(v0, v1, hi, lo);
        g_Wh[n * 128 + kp]  = hi;
        g_Wlo[n * 128 + kp] = lo;
        return;
    }
    if (b < 66) {
#pragma unroll
        for (int i = 0; i < 8; ++i) wcs[tid + i * 256] = Wc[tid + i * 256];
        __syncthreads();
        if (tid < 128) {
            const float* Win = (b == 64) ? W2_l : W2_r;
            float* Wout      = (b == 64) ? g_Wlc : g_Wrc;
            float4 a0 = make_float4(0,0,0,0), a1 = a0, a2 = a0, a3 = a0;
            const float* row = Win + tid * HIDDEN;
#pragma unroll 4
            for (int t = 0; t < HIDDEN; ++t) {
                float w = row[t];
                float4 c0 = *(const float4*)&wcs[t * 16 + 0];
                float4 c1 = *(const float4*)&wcs[t * 16 + 4];
                float4 c2 = *(const float4*)&wcs[t * 16 + 8];
                float4 c3 = *(const float4*)&wcs[t * 16 + 12];
                a0.x = fmaf(w, c0.x, a0.x); a0.y = fmaf(w, c0.y, a0.y);
                a0.z = fmaf(w, c0.z, a0.z); a0.w = fmaf(w, c0.w, a0.w);
                a1.x = fmaf(w, c1.x, a1.x); a1.y = fmaf(w, c1.y, a1.y);
                a1.z = fmaf(w, c1.z, a1.z); a1.w = fmaf(w, c1.w, a1.w);
                a2.x = fmaf(w, c2.x, a2.x); a2.y = fmaf(w, c2.y, a2.y);
                a2.z = fmaf(w, c2.z, a2.z); a2.w = fmaf(w, c2.w, a2.w);
                a3.x = fmaf(w, c3.x, a3.x); a3.y = fmaf(w, c3.y, a3.y);
                a3.z = fmaf(w, c3.z, a3.z); a3.w = fmaf(w, c3.w, a3.w);
            }
            *(float4*)&Wout[tid * 16 + 0]  = a0;
            *(float4*)&Wout[tid * 16 + 4]  = a1;
            *(float4*)&Wout[tid * 16 + 8]  = a2;
            *(float4*)&Wout[tid * 16 + 12] = a3;

            if (b == 65 && tid < NUM_TYPES) {
                float s = bc[tid];
                for (int t = 0; t < HIDDEN; ++t) s = fmaf(b2[t], wcs[t * 16 + tid], s);
                g_bf[tid] = s;
            }
        }
        return;
    }
    int idx = (b - 66) * 256 + tid;
    if (idx < N_NODES) g_deg[idx] = 0;
}

// ---------------------------------------------------------------------------
// Kernel: fused x-gather + degree count (deg pre-zeroed by k_init).
//   blocks [0, PREP_BLOCKS): x = emb[entity], warp per node
//   blocks [PREP_BLOCKS, ..): deg atomics over edges
// ---------------------------------------------------------------------------
#define PREP_BLOCKS ((N_NODES + 7) / 8)                  // 6250
#define DEG_BLOCKS  ((N_EDGES + 255) / 256)              // 2344

__global__ void k_prepdeg(const int* __restrict__ entity,
                          const float* __restrict__ emb,
                          const int* __restrict__ dst) {
    if (blockIdx.x < PREP_BLOCKS) {
        int node = blockIdx.x * 8 + (threadIdx.x >> 5);
        int lane = threadIdx.x & 31;
        if (node >= N_NODES) return;
        int e = entity[node];
        float4 v = ((const float4*)emb)[e * 32 + lane];
        ((float4*)g_x)[node * 32 + lane] = v;
    } else {
        int e = (blockIdx.x - PREP_BLOCKS) * 256 + threadIdx.x;
        if (e < N_EDGES) atomicAdd(&g_deg[dst[e]], 1);
    }
}

// ---------------------------------------------------------------------------
// Fused scan1+scan2: per-block sum, last block scans the block sums.
// ---------------------------------------------------------------------------
__global__ void __launch_bounds__(256) k_scanA() {
    __shared__ int s[256];
    __shared__ bool amlast;
    int idx = blockIdx.x * 256 + threadIdx.x;
    int t = threadIdx.x;
    int v = (idx < N_NODES) ? g_deg[idx] : 0;
    s[t] = v;
    __syncthreads();
#pragma unroll
    for (int off = 128; off > 0; off >>= 1) {
        if (t < off) s[t] += s[t + off];
        __syncthreads();
    }
    if (t == 0) {
        g_bsum[blockIdx.x] = s[0];
        __threadfence();
        int prev = atomicAdd(&g_scancnt, 1);
        amlast = (prev == (int)gridDim.x - 1);
    }
    __syncthreads();
    if (amlast) {
        // exclusive scan over gridDim.x block sums
        int nb = gridDim.x;
        int vv = (t < nb) ? g_bsum[t] : 0;
        s[t] = vv;
        __syncthreads();
#pragma unroll
        for (int off = 1; off < 256; off <<= 1) {
            int x = (t >= off) ? s[t - off] : 0;
            __syncthreads();
            s[t] += x;
            __syncthreads();
        }
        if (t < nb) g_bsum[t] = s[t] - vv;
        if (t == 0) g_scancnt = 0;   // reset for next graph replay
    }
}

__global__ void __launch_bounds__(256) k_scan3() {
    __shared__ int s[256];
    int idx = blockIdx.x * 256 + threadIdx.x;
    int t = threadIdx.x;
    int v = (idx < N_NODES) ? g_deg[idx] : 0;
    s[t] = v;
    __syncthreads();
#pragma unroll
    for (int off = 1; off < 256; off <<= 1) {
        int x = (t >= off) ? s[t - off] : 0;
        __syncthreads();
        s[t] += x;
        __syncthreads();
    }
    if (idx < N_NODES) {
        int excl = g_bsum[blockIdx.x] + s[t] - v;
        g_rowptr[idx] = excl;
        g_cursor[idx] = excl;
        if (idx == N_NODES - 1) g_rowptr[N_NODES] = excl + v;
    }
}

__global__ void k_fill(const int* __restrict__ src, const int* __restrict__ dst) {
    int e = blockIdx.x * blockDim.x + threadIdx.x;
    if (e >= N_EDGES) return;
    int d = dst[e];
    int pos = atomicAdd(&g_cursor[d], 1);
    g_csrc[pos] = src[e];
}

// ---------------------------------------------------------------------------
// Kernel: gather-aggregate 128-wide. One warp per node; writes the MEAN.
// ---------------------------------------------------------------------------
__global__ void __launch_bounds__(256) k_gather(void) {
    int node = blockIdx.x * 8 + (threadIdx.x >> 5);
    int lane = threadIdx.x & 31;
    if (node >= N_NODES) return;
    int start = g_rowptr[node];
    int end   = g_rowptr[node + 1];

    float4 a0 = make_float4(0.f, 0.f, 0.f, 0.f);
    float4 a1 = a0, a2 = a0, a3 = a0;
    int j = start;
    for (; j + 3 < end; j += 4) {
        int s0 = g_csrc[j];
        int s1 = g_csrc[j + 1];
        int s2 = g_csrc[j + 2];
        int s3 = g_csrc[j + 3];
        float4 v0 = ((const float4*)g_x)[s0 * 32 + lane];
        float4 v1 = ((const float4*)g_x)[s1 * 32 + lane];
        float4 v2 = ((const float4*)g_x)[s2 * 32 + lane];
        float4 v3 = ((const float4*)g_x)[s3 * 32 + lane];
        a0.x += v0.x; a0.y += v0.y; a0.z += v0.z; a0.w += v0.w;
        a1.x += v1.x; a1.y += v1.y; a1.z += v1.z; a1.w += v1.w;
        a2.x += v2.x; a2.y += v2.y; a2.z += v2.z; a2.w += v2.w;
        a3.x += v3.x; a3.y += v3.y; a3.z += v3.z; a3.w += v3.w;
    }
    for (; j < end; ++j) {
        int s0 = g_csrc[j];
        float4 v0 = ((const float4*)g_x)[s0 * 32 + lane];
        a0.x += v0.x; a0.y += v0.y; a0.z += v0.z; a0.w += v0.w;
    }
    int dg = end - start;
    float inv = 1.0f / (float)(dg > 1 ? dg : 1);
    float4 r = make_float4((a0.x + a1.x + a2.x + a3.x) * inv,
                           (a0.y + a1.y + a2.y + a3.y) * inv,
                           (a0.z + a1.z + a2.z + a3.z) * inv,
                           (a0.w + a1.w + a2.w + a3.w) * inv);
    ((float4*)g_agg)[node * 32 + lane] = r;
}

// ---------------------------------------------------------------------------
// Kernel 4: SAGE layer-1 via mma.sync bf16 m16n8k16 (3-way split), relu.
// R9 config: BM=128, BN=128, 8 warps (4m x 2n), warp tile 32x64,
// double-buffered 48KB smem, one __syncthreads per 16-k chunk.
// ---------------------------------------------------------------------------
__global__ void __launch_bounds__(256, 2) k_layer_bf16(
        const float* __restrict__ bias, const float* __restrict__ xin,
        float* __restrict__ outp) {
    extern __shared__ uint32_t dsm[];

    const int tid = threadIdx.x;
    const int m0  = blockIdx.x * 128;

    uint32_t* sAh[2] = { dsm + 0 * 1536, dsm + 2 * 1536 };
    uint32_t* sAl[2] = { dsm + 1 * 1536, dsm + 3 * 1536 };
    uint32_t* sBh[2] = { dsm + 6144 + 0 * 1536, dsm + 6144 + 2 * 1536 };
    uint32_t* sBl[2] = { dsm + 6144 + 1 * 1536, dsm + 6144 + 3 * 1536 };

    const int w    = tid >> 5;
    const int lane = tid & 31;
    const int g    = lane >> 2;
    const int tg   = lane & 3;
    const int wm   = (w >> 1) << 5;     // 0,32,64,96
    const int wn   = (w & 1) << 6;      // 0,64

    const int a_m[2]  = { (tid + 0) >> 2,   (tid + 256) >> 2 };
    const int a_kq[2] = { (tid & 3) << 2,   (tid & 3) << 2 };
    const int b_n    = tid >> 1;
    const int b_half = (tid & 1) << 2;

    float acc[2][8][4];
#pragma unroll
    for (int mt = 0; mt < 2; ++mt)
#pragma unroll
        for (int nt = 0; nt < 8; ++nt)
#pragma unroll
            for (int q = 0; q < 4; ++q) acc[mt][nt][q] = 0.f;

    float4 aIn[2];
    uint4  bInH, bInL;

#define LOAD_AB(c) do {                                                        \
        const int kb = (c) * 16;                                               \
        _Pragma("unroll")                                                      \
        for (int it = 0; it < 2; ++it) {                                       \
            const int m  = a_m[it];                                            \
            const int gm = m0 + m;                                             \
            float4 v = make_float4(0.f, 0.f, 0.f, 0.f);                        \
            if (gm < N_NODES) {                                                \
                if (kb < 128) {                                                \
                    v = *(const float4*)(g_agg + (size_t)gm * 128 + kb + a_kq[it]); \
                } else {                                                       \
                    v = *(const float4*)(xin + (size_t)gm * 128 + (kb - 128) + a_kq[it]); \
                }                                                              \
            }                                                                  \
            aIn[it] = v;                                                       \
        }                                                                      \
        {                                                                      \
            const int goff = b_n * 128 + (c) * 8 + b_half;                     \
            bInH = *(const uint4*)&g_Wh[goff];                                 \
            bInL = *(const uint4*)&g_Wlo[goff];                                \
        }                                                                      \
    } while (0)

#define STORE_AB(buf) do {                                                     \
        _Pragma("unroll")                                                      \
        for (int it = 0; it < 2; ++it) {                                       \
            const float4 v = aIn[it];                                          \
            uint32_t h0, l0, h1, l1;                                           \
            split2(v.x, v.y, h0, l0);                                          \
            split2(v.z, v.w, h1, l1);                                          \
            const int base = a_m[it] * 12 + (a_kq[it] >> 1);                   \
            sAh[buf][base]     = h0;                                           \
            sAh[buf][base + 1] = h1;                                           \
            sAl[buf][base]     = l0;                                           \
            sAl[buf][base + 1] = l1;                                           \
        }                                                                      \
        {                                                                      \
            const int base = b_n * 12 + b_half;                                \
            *(uint4*)&sBh[buf][base] = bInH;                                   \
            *(uint4*)&sBl[buf][base] = bInL;                                   \
        }                                                                      \
    } while (0)

    LOAD_AB(0);
    STORE_AB(0);
    __syncthreads();

    for (int c = 0; c < 16; ++c) {
        const int cur = c & 1;
        if (c < 15) LOAD_AB(c + 1);

        const uint32_t* Ah = sAh[cur];
        const uint32_t* Al = sAl[cur];
        const uint32_t* Bh = sBh[cur];
        const uint32_t* Bl = sBl[cur];

        uint32_t ah[2][4], al[2][4];
#pragma unroll
        for (int mt = 0; mt < 2; ++mt) {
            const int mb = wm + mt * 16;
            const int r0 = (mb + g) * 12;
            const int r1 = (mb + g + 8) * 12;
            ah[mt][0] = Ah[r0 + tg];
            ah[mt][1] = Ah[r1 + tg];
            ah[mt][2] = Ah[r0 + tg + 4];
            ah[mt][3] = Ah[r1 + tg + 4];
            al[mt][0] = Al[r0 + tg];
            al[mt][1] = Al[r1 + tg];
            al[mt][2] = Al[r0 + tg + 4];
            al[mt][3] = Al[r1 + tg + 4];
        }
#pragma unroll
        for (int nt = 0; nt < 8; ++nt) {
            const int nb = (wn + nt * 8 + g) * 12;
            uint32_t bh[2] = { Bh[nb + tg], Bh[nb + tg + 4] };
            uint32_t bl[2] = { Bl[nb + tg], Bl[nb + tg + 4] };
#pragma unroll
            for (int mt = 0; mt < 2; ++mt) {
                mma16(acc[mt][nt], ah[mt], bh);
                mma16(acc[mt][nt], al[mt], bh);
                mma16(acc[mt][nt], ah[mt], bl);
            }
        }

        if (c < 15) STORE_AB(cur ^ 1);
        __syncthreads();
    }
#undef LOAD_AB
#undef STORE_AB

    // epilogue: bias + relu + float2 stores
#pragma unroll
    for (int nt = 0; nt < 8; ++nt) {
        const int col = wn + nt * 8 + 2 * tg;
        const float2 bv = *(const float2*)(bias + col);
#pragma unroll
        for (int mt = 0; mt < 2; ++mt) {
            const int r0 = m0 + wm + mt * 16 + g;
            const int r1 = r0 + 8;
            float v0 = acc[mt][nt][0] + bv.x;
            float v1 = acc[mt][nt][1] + bv.y;
            float v2 = acc[mt][nt][2] + bv.x;
            float v3 = acc[mt][nt][3] + bv.y;
            v0 = v0 > 0.f ? v0 : 0.f;
            v1 = v1 > 0.f ? v1 : 0.f;
            v2 = v2 > 0.f ? v2 : 0.f;
            v3 = v3 > 0.f ? v3 : 0.f;
            if (r0 < N_NODES)
                *(float2*)(outp + (size_t)r0 * 128 + col) = make_float2(v0, v1);
            if (r1 < N_NODES)
                *(float2*)(outp + (size_t)r1 * 128 + col) = make_float2(v2, v3);
        }
    }
}

// ---------------------------------------------------------------------------
// Kernel: z = h1 @ Wlc ; r = h1 @ Wrc + bf.
// ---------------------------------------------------------------------------
__global__ void __launch_bounds__(256) k_zr(const float* __restrict__ h1) {
    __shared__ float hs[16][128];
    __shared__ float wl[16][132];
    __shared__ float wr[16][132];
    __shared__ float bfs[16];
    const int tid = threadIdx.x;

#pragma unroll
    for (int i = 0; i < 8; ++i) {
        int idx = tid + i * 256;
        int k = idx >> 4, c = idx & 15;
        wl[c][k] = g_Wlc[idx];
        wr[c][k] = g_Wrc[idx];
    }
    if (tid < 16) bfs[tid] = g_bf[tid];

    const int n0 = blockIdx.x * 16;
#pragma unroll
    for (int i = 0; i < 2; ++i) {
        int idx = tid + i * 256;
        int rr = n0 + (idx >> 5);
        float4 v = (rr < N_NODES) ? ((const float4*)h1)[rr * 32 + (idx & 31)]
                                  : make_float4(0.f, 0.f, 0.f, 0.f);
        ((float4*)&hs[0][0])[idx] = v;
    }
    __syncthreads();

    const int node = tid >> 4;
    const int col  = tid & 15;
    float zs = 0.f, rs = bfs[col];
#pragma unroll
    for (int k4 = 0; k4 < 32; ++k4) {
        float4 h = *(const float4*)&hs[node][k4 * 4];
        float4 a = *(const float4*)&wl[col][k4 * 4];
        float4 b = *(const float4*)&wr[col][k4 * 4];
        zs = fmaf(h.x, a.x, zs); zs = fmaf(h.y, a.y, zs);
        zs = fmaf(h.z, a.z, zs); zs = fmaf(h.w, a.w, zs);
        rs = fmaf(h.x, b.x, rs); rs = fmaf(h.y, b.y, rs);
        rs = fmaf(h.z, b.z, rs); rs = fmaf(h.w, b.w, rs);
    }
    int gn = n0 + node;
    if (gn < N_NODES) {
        g_z[gn * 16 + col] = zs;
        g_r[gn * 16 + col] = rs;
    }
}

// ---------------------------------------------------------------------------
// Kernel: out[n,c] = mean_{j->n}(z[j,c]) + r[n,c]   (gather, fused comb)
// ---------------------------------------------------------------------------
__global__ void __launch_bounds__(256) k_comb2(float* __restrict__ out) {
    int idx = blockIdx.x * 256 + threadIdx.x;
    int n = idx >> 4;
    if (n >= N_NODES) return;
    int c = idx & 15;
    int start = g_rowptr[n];
    int end   = g_rowptr[n + 1];
    float a0 = 0.f, a1 = 0.f, a2 = 0.f, a3 = 0.f;
    int j = start;
    for (; j + 3 < end; j += 4) {
        int s0 = g_csrc[j];
        int s1 = g_csrc[j + 1];
        int s2 = g_csrc[j + 2];
        int s3 = g_csrc[j + 3];
        a0 += g_z[s0 * 16 + c];
        a1 += g_z[s1 * 16 + c];
        a2 += g_z[s2 * 16 + c];
        a3 += g_z[s3 * 16 + c];
    }
    for (; j < end; ++j) a0 += g_z[g_csrc[j] * 16 + c];
    int dg = end - start;
    float inv = 1.0f / (float)(dg > 1 ? dg : 1);
    out[idx] = fmaf((a0 + a1) + (a2 + a3), inv, g_r[idx]);
}

// ---------------------------------------------------------------------------
extern "C" void kernel_launch(void* const* d_in, const int* in_sizes, int n_in,
                              void* d_out, int out_size) {
    const int*   entity = (const int*)d_in[0];
    const int*   eidx   = (const int*)d_in[1];
    const float* emb    = (const float*)d_in[2];
    const float* W1_l   = (const float*)d_in[3];
    const float* b1     = (const float*)d_in[4];
    const float* W1_r   = (const float*)d_in[5];
    const float* W2_l   = (const float*)d_in[6];
    const float* b2     = (const float*)d_in[7];
    const float* W2_r   = (const float*)d_in[8];
    const float* Wc     = (const float*)d_in[9];
    const float* bc     = (const float*)d_in[10];
    float* out = (float*)d_out;

    const int* src = eidx;            // edge_index[0]
    const int* dst = eidx + N_EDGES;  // edge_index[1]

    float* d_x  = nullptr; cudaGetSymbolAddress((void**)&d_x,  g_x);
    float* d_h1 = nullptr; cudaGetSymbolAddress((void**)&d_h1, g_h1);

    const int GEMM_BLOCKS = (N_NODES + 127) / 128;     // 391
    const int SCAN_BLOCKS = (N_NODES + 255) / 256;     // 196
    const int INIT_BLOCKS = 66 + SCAN_BLOCKS;          // wprep + wfuse + degzero
    const int SMEM_LAYER  = 48 * 1024;

    cudaFuncSetAttribute(k_layer_bf16, cudaFuncAttributeMaxDynamicSharedMemorySize,
                         SMEM_LAYER);

    // merged weight precompute + deg zero
    k_init<<<INIT_BLOCKS, 256>>>(W1_l, W1_r, W2_l, W2_r, Wc, b2, bc);
    // fused x-gather + degree count
    k_prepdeg<<<PREP_BLOCKS + DEG_BLOCKS, 256>>>(entity, emb, dst);
    // CSR build (scan1+scan2 fused; scan3; fill)
    k_scanA<<<SCAN_BLOCKS, 256>>>();
    k_scan3<<<SCAN_BLOCKS, 256>>>();
    k_fill<<<(N_EDGES + 255) / 256, 256>>>(src, dst);
    // gather-aggregate mean of x
    k_gather<<<(N_NODES + 7) / 8, 256>>>();
    // layer 1 (relu) -> h1  (R9 config)
    k_layer_bf16<<<GEMM_BLOCKS, 256, SMEM_LAYER>>>(b1, d_x, d_h1);
    // z = h1@Wlc, r = h1@Wrc + bf
    k_zr<<<(N_NODES + 15) / 16, 256>>>(d_h1);
    // fused gather mean of z + combine
    k_comb2<<<(N_NODES * 16 + 255) / 256, 256>>>(out);
}